// round 11
// baseline (speedup 1.0000x reference)
#include <cuda_runtime.h>
#include <math.h>
#include <stdint.h>

#define BB 128
#define TT 1024
#define DD 43
#define HH 256
#define G4 1024

// ---- static device scratch (allocation-free) ----
__device__ float g_xg[(size_t)TT * BB * G4];   // [t][b][g]
__device__ float g_hs[(size_t)BB * TT * HH];   // [b][t][k]
__device__ float g_a1[(size_t)BB * TT * HH];   // [tok][k]

__device__ __forceinline__ float sigf(float x) {
    float y;
    asm("tanh.approx.f32 %0, %1;" : "=f"(y) : "f"(0.5f * x));
    return 0.5f * y + 0.5f;
}
__device__ __forceinline__ float tanhf_fast(float x) {
    float y;
    asm("tanh.approx.f32 %0, %1;" : "=f"(y) : "f"(x));
    return y;
}
__device__ __forceinline__ uint32_t smem_u32(const void* p) {
    uint32_t a;
    asm("{ .reg .u64 t; cvta.to.shared.u64 t, %1; cvt.u32.u64 %0, t; }" : "=r"(a) : "l"(p));
    return a;
}

#define UNPACK2(lo, hi, s) asm("mov.b64 {%0, %1}, %2;" : "=f"(lo), "=f"(hi) : "l"(s))
#define FFMA2(acc, a, b)   asm("fma.rn.f32x2 %0, %1, %2, %0;" : "+l"(acc) : "l"(a), "l"(b))

// ---------------------------------------------------------------------------
// Kernel A: xg[t][b][g] = xin[b,t,:] . W_ih[g,:] + b_ih[g] + b_hh[g]
// ---------------------------------------------------------------------------
__global__ void __launch_bounds__(256) kA(const float* __restrict__ x,
                                          const float* __restrict__ Wih,
                                          const float* __restrict__ bih,
                                          const float* __restrict__ bhh) {
    __shared__ float xin[32 * 44];
    const int tid = threadIdx.x;
    const int g0  = blockIdx.x * 256;
    const int t0  = blockIdx.y * 32;
    const int b   = blockIdx.z;

    for (int e = tid; e < 32 * 44; e += 256) {
        int tt = e / 44, d = e % 44;
        int t = t0 + tt;
        float v = 0.0f;
        if (d < 35)      v = x[((size_t)b * TT + t) * DD + d];
        else if (d < 43) { if (t > 0) v = x[((size_t)b * TT + t - 1) * DD + d]; }
        xin[e] = v;
    }

    const int g = g0 + tid;
    float w[44];
#pragma unroll
    for (int d = 0; d < 43; d++) w[d] = Wih[g * DD + d];
    w[43] = 0.0f;
    const float bias = bih[g] + bhh[g];
    __syncthreads();

#pragma unroll 4
    for (int tt = 0; tt < 32; tt++) {
        const float* xr = &xin[tt * 44];
        float acc = bias;
#pragma unroll
        for (int d = 0; d < 44; d++) acc += w[d] * xr[d];
        g_xg[((size_t)(t0 + tt) * BB + b) * G4 + g] = acc;
    }
}

// ---------------------------------------------------------------------------
// Kernel B: persistent LSTM, 16 clusters of 8 CTAs (batch-group x hidden-slice).
// 1024 threads, 4-way K-split f32x2 GEMM. h data via g_hs in L2; per-step sync
// via cluster mbarrier (remote release-arrive + local parity acquire-wait).
// ---------------------------------------------------------------------------
#define WSTR     260
#define HS_OFF   (128 * WSTR)              // hsh: [8][260]
#define GS_OFF   (HS_OFF + 8 * WSTR)       // gsh: [4][128*9]
#define MBAR_OFF ((GS_OFF + 4 * 128 * 9) * 4)
#define SMEM_B   (MBAR_OFF + 16)

__global__ void __launch_bounds__(1024, 1) __cluster_dims__(8, 1, 1)
kB(const float* __restrict__ Whh) {
    extern __shared__ float sm[];
    float* Wsh = sm;                   // [128][260]
    float* hsh = sm + HS_OFF;          // [8][260]    h(t-1), [batch][k]
    float* gsh = sm + GS_OFF;          // [4][128*9]  K-quarter partial gates

    const int tid = threadIdx.x;
    const int cta = blockIdx.x;
    const int bg  = cta >> 3;          // batch group 0..15
    const int hsl = cta & 7;           // hidden slice = cluster rank
    const int b0  = bg * 8;

    const uint32_t smb  = smem_u32(sm);
    const uint32_t mbar = smb + MBAR_OFF;

    if (tid == 0)
        asm volatile("mbarrier.init.shared.b64 [%0], %1;" :: "r"(mbar), "r"(8) : "memory");

    // load W_hh slice: local row r -> global row (r>>5)*256 + hsl*32 + (r&31)
    for (int e = tid; e < 128 * 256; e += 1024) {
        int r = e >> 8, k = e & 255;
        int R = ((r >> 5) << 8) + hsl * 32 + (r & 31);
        Wsh[r * WSTR + k] = Whh[R * 256 + k];
    }
    // h(-1) = 0
    for (int e = tid; e < 8 * WSTR; e += 1024) hsh[e] = 0.0f;
    __syncthreads();
    asm volatile("barrier.cluster.arrive.aligned;" ::: "memory");
    asm volatile("barrier.cluster.wait.aligned;" ::: "memory");

    // GEMM mapping: kh = K-quarter, r = gate row, bh = batch half
    const int kh  = tid >> 8;          // 0..3
    const int sub = tid & 255;
    const int r   = sub >> 1;          // 0..127
    const int bh  = sub & 1;
    // pointwise mapping (tid < 256)
    const int ub = sub >> 5;           // batch 0..7
    const int uk = sub & 31;           // local hidden 0..31
    // stage mapping (tid < 512)
    const int sb = (tid >> 6) & 7;     // batch 0..7
    const int sk = tid & 63;           // k-quad 0..63

    // remote mbarrier address for arriving threads (tid < 8 -> rank tid)
    uint32_t rmbar = 0;
    if (tid < 8)
        asm("mapa.shared::cluster.u32 %0, %1, %2;" : "=r"(rmbar) : "r"(mbar), "r"(tid));

    float c = 0.0f;

    // prefetch xg[0] (pointwise threads)
    float px0, px1, px2, px3;
    if (tid < 256) {
        const float* p = &g_xg[((size_t)b0 + ub) * G4 + hsl * 32 + uk];
        px0 = __ldcg(p);       px1 = __ldcg(p + 256);
        px2 = __ldcg(p + 512); px3 = __ldcg(p + 768);
    }

    for (int t = 0; t < TT; t++) {
        // prefetch next step's xg (covered by GEMM)
        float nx0, nx1, nx2, nx3;
        if (tid < 256) {
            int tn = (t + 1 < TT) ? (t + 1) : t;
            const float* p = &g_xg[((size_t)tn * BB + b0 + ub) * G4 + hsl * 32 + uk];
            nx0 = __ldcg(p);       nx1 = __ldcg(p + 256);
            nx2 = __ldcg(p + 512); nx3 = __ldcg(p + 768);
        }

        // ---- GEMM partial: K-quarter, 4 batches, f32x2 pairs over K ----
        {
            unsigned long long a0 = 0, a1 = 0, a2 = 0, a3 = 0;
            const ulonglong2* wp = (const ulonglong2*)&Wsh[r * WSTR + kh * 64];
            const ulonglong2* h0 = (const ulonglong2*)&hsh[(bh * 4 + 0) * WSTR + kh * 64];
            const ulonglong2* h1 = (const ulonglong2*)&hsh[(bh * 4 + 1) * WSTR + kh * 64];
            const ulonglong2* h2 = (const ulonglong2*)&hsh[(bh * 4 + 2) * WSTR + kh * 64];
            const ulonglong2* h3 = (const ulonglong2*)&hsh[(bh * 4 + 3) * WSTR + kh * 64];
#pragma unroll
            for (int i = 0; i < 16; i++) {
                ulonglong2 w = wp[i];
                ulonglong2 q0 = h0[i];
                FFMA2(a0, w.x, q0.x); FFMA2(a0, w.y, q0.y);
                ulonglong2 q1 = h1[i];
                FFMA2(a1, w.x, q1.x); FFMA2(a1, w.y, q1.y);
                ulonglong2 q2 = h2[i];
                FFMA2(a2, w.x, q2.x); FFMA2(a2, w.y, q2.y);
                ulonglong2 q3 = h3[i];
                FFMA2(a3, w.x, q3.x); FFMA2(a3, w.y, q3.y);
            }
            float lo, hi, s0, s1, s2, s3;
            UNPACK2(lo, hi, a0); s0 = lo + hi;
            UNPACK2(lo, hi, a1); s1 = lo + hi;
            UNPACK2(lo, hi, a2); s2 = lo + hi;
            UNPACK2(lo, hi, a3); s3 = lo + hi;
            float* gp = &gsh[kh * (128 * 9) + r * 9 + bh * 4];
            gp[0] = s0; gp[1] = s1; gp[2] = s2; gp[3] = s3;
        }
        __syncthreads();

        // ---- pointwise LSTM update (tid < 256) ----
        if (tid < 256) {
            const int o = uk * 9 + ub;
            float gi = px0 + gsh[o]            + gsh[1152 + o]
                           + gsh[2304 + o]     + gsh[3456 + o];
            float gf = px1 + gsh[288 + o]      + gsh[1152 + 288 + o]
                           + gsh[2304 + 288 + o] + gsh[3456 + 288 + o];
            float gg = px2 + gsh[576 + o]      + gsh[1152 + 576 + o]
                           + gsh[2304 + 576 + o] + gsh[3456 + 576 + o];
            float go = px3 + gsh[864 + o]      + gsh[1152 + 864 + o]
                           + gsh[2304 + 864 + o] + gsh[3456 + 864 + o];
            gi = sigf(gi); gf = sigf(gf);
            gg = tanhf_fast(gg); go = sigf(go);
            c = gf * c + gi * gg;
            float h = go * tanhf_fast(c);
            g_hs[(((size_t)(b0 + ub)) * TT + t) * HH + hsl * 32 + uk] = h;
            hsh[ub * WSTR + hsl * 32 + uk] = h;     // own slice locally
            px0 = nx0; px1 = nx1; px2 = nx2; px3 = nx3;
        }

        if (t + 1 < TT) {
            __syncthreads();                         // h STG/STS visible
            // release-arrive on every peer's mbarrier (threads 0..7)
            if (tid < 8)
                asm volatile("mbarrier.arrive.release.cluster.shared::cluster.b64 _, [%0];"
                             :: "r"(rmbar) : "memory");
            // all threads: acquire-wait for all 8 slices' arrivals
            {
                const uint32_t parity = (uint32_t)(t & 1);
                uint32_t done;
                asm volatile(
                    "{\n\t.reg .pred p;\n\t"
                    "mbarrier.try_wait.parity.acquire.cluster.shared::cta.b64 p, [%1], %2;\n\t"
                    "selp.b32 %0, 1, 0, p;\n\t}"
                    : "=r"(done) : "r"(mbar), "r"(parity) : "memory");
                if (!done) {
                    asm volatile(
                        "{\n\t.reg .pred P1;\n\t"
                        "WAIT_B_%=:\n\t"
                        "mbarrier.try_wait.parity.acquire.cluster.shared::cta.b64 P1, [%0], %1, 0x989680;\n\t"
                        "@P1 bra.uni DONE_B_%=;\n\t"
                        "bra.uni WAIT_B_%=;\n\t"
                        "DONE_B_%=:\n\t}"
                        :: "r"(mbar), "r"(parity) : "memory");
                }
            }
            // ---- stage remote slices of h(t) -> hsh[b][k] ----
            if (tid < 512 && (sk >> 3) != hsl) {
                float4 v = __ldcg((const float4*)
                    &g_hs[(((size_t)(b0 + sb)) * TT + t) * HH + sk * 4]);
                *(float4*)&hsh[sb * WSTR + sk * 4] = v;
            }
            __syncthreads();
        }
    }

    asm volatile("barrier.cluster.arrive.aligned;" ::: "memory");
    asm volatile("barrier.cluster.wait.aligned;" ::: "memory");
}

// ---------------------------------------------------------------------------
// Kernel C1: a1 = relu(hs @ W_afc1^T + b).  Block: 32 tokens x 256 outputs.
// ---------------------------------------------------------------------------
#define SMEM_C1 ((32 * 256 + 256 * 68) * 4)

__global__ void __launch_bounds__(256) kC1(const float* __restrict__ Wa,
                                           const float* __restrict__ ba) {
    extern __shared__ float sm[];
    float* hsh = sm;               // [32][256]
    float* Ws  = sm + 32 * 256;    // [256][68] current K-chunk

    const int tid  = threadIdx.x;
    const int tok0 = blockIdx.x * 32;

    for (int e = tid; e < 32 * 256; e += 256)
        hsh[e] = g_hs[(size_t)tok0 * 256 + e];

    float acc[32];
    const float bias = ba[tid];
#pragma unroll
    for (int i = 0; i < 32; i++) acc[i] = bias;

    for (int kc = 0; kc < 4; kc++) {
        __syncthreads();
        for (int e = tid; e < 256 * 64; e += 256) {
            int j = e >> 6, kk = e & 63;
            Ws[j * 68 + kk] = Wa[j * 256 + kc * 64 + kk];
        }
        __syncthreads();
        const float4* wp = (const float4*)&Ws[tid * 68];
#pragma unroll
        for (int q = 0; q < 16; q++) {
            float4 w4 = wp[q];
            const int kbase = kc * 64 + q * 4;
#pragma unroll 8
            for (int tt = 0; tt < 32; tt++) {
                float4 h = *(const float4*)&hsh[tt * 256 + kbase];
                acc[tt] += w4.x * h.x + w4.y * h.y + w4.z * h.z + w4.w * h.w;
            }
        }
    }
#pragma unroll
    for (int tt = 0; tt < 32; tt++)
        g_a1[((size_t)(tok0 + tt)) * 256 + tid] = fmaxf(acc[tt], 0.0f);
}

// ---------------------------------------------------------------------------
// Kernel C2: cont / bin / act heads.
// ---------------------------------------------------------------------------
#define CONT_BASE 0
#define BIN_BASE  (128 * 1024 * 50)
#define ACT_BASE  (BIN_BASE + 128 * 1024 * 10)
#define SMEM_C2 ((32 * 268 + 32 * 256 + 50 * 268 + 10 * 268 + 8 * 256 + 68) * 4)

__global__ void __launch_bounds__(256) kC2(const float* __restrict__ x,
                                           const float* __restrict__ Wao,
                                           const float* __restrict__ bao,
                                           const float* __restrict__ Wc,
                                           const float* __restrict__ bc,
                                           const float* __restrict__ Wb,
                                           const float* __restrict__ bb,
                                           float* __restrict__ out) {
    extern __shared__ float sm[];
    float* pred = sm;                   // [32][268]  (h | cur)
    float* a1s  = pred + 32 * 268;      // [32][256]
    float* Wcs  = a1s  + 32 * 256;      // [50][268]
    float* Wbs  = Wcs  + 50 * 268;      // [10][268]
    float* Was  = Wbs  + 10 * 268;      // [8][256]
    float* bcs  = Was  + 8 * 256;       // 50
    float* bbs  = bcs + 50;             // 10
    float* bas  = bbs + 10;             // 8

    const int tid  = threadIdx.x;
    const int tok0 = blockIdx.x * 32;

    for (int e = tid; e < 32 * 256; e += 256) {
        int tt = e >> 8, k = e & 255;
        pred[tt * 268 + k] = g_hs[(size_t)tok0 * 256 + e];
        a1s[e]             = g_a1[(size_t)tok0 * 256 + e];
    }
    if (tid < 32 * 8) {
        int tt = tid >> 3, j = tid & 7;
        pred[tt * 268 + 256 + j] = x[((size_t)(tok0 + tt)) * DD + 35 + j];
    }
    for (int e = tid; e < 50 * 264; e += 256) {
        int o = e / 264, d = e % 264;
        Wcs[o * 268 + d] = Wc[e];
    }
    for (int e = tid; e < 10 * 264; e += 256) {
        int o = e / 264, d = e % 264;
        Wbs[o * 268 + d] = Wb[e];
    }
    for (int e = tid; e < 8 * 256; e += 256) Was[e] = Wao[e];
    if (tid < 50) bcs[tid] = bc[tid];
    if (tid < 10) bbs[tid] = bb[tid];
    if (tid < 8)  bas[tid] = bao[tid];
    __syncthreads();

    for (int idx = tid; idx < 32 * 68; idx += 256) {
        const int tt   = idx / 68;
        const int o    = idx % 68;
        const int gtok = tok0 + tt;
        if (o < 50) {
            float acc = bcs[o];
            const float4* wp = (const float4*)&Wcs[o * 268];
            const float4* pp = (const float4*)&pred[tt * 268];
#pragma unroll 11
            for (int q = 0; q < 66; q++) {
                float4 w = wp[q], p = pp[q];
                acc += w.x * p.x + w.y * p.y + w.z * p.z + w.w * p.w;
            }
            out[CONT_BASE + (size_t)gtok * 50 + o] = acc;
        } else if (o < 60) {
            const int o2 = o - 50;
            float acc = bbs[o2];
            const float4* wp = (const float4*)&Wbs[o2 * 268];
            const float4* pp = (const float4*)&pred[tt * 268];
#pragma unroll 11
            for (int q = 0; q < 66; q++) {
                float4 w = wp[q], p = pp[q];
                acc += w.x * p.x + w.y * p.y + w.z * p.z + w.w * p.w;
            }
            out[BIN_BASE + (size_t)gtok * 10 + o2] = 1.0f / (1.0f + __expf(-acc));
        } else {
            const int o3 = o - 60;
            float acc = bas[o3];
            const float4* wp = (const float4*)&Was[o3 * 256];
            const float4* pp = (const float4*)&a1s[tt * 256];
#pragma unroll 16
            for (int q = 0; q < 64; q++) {
                float4 w = wp[q], p = pp[q];
                acc += w.x * p.x + w.y * p.y + w.z * p.z + w.w * p.w;
            }
            out[ACT_BASE + (size_t)gtok * 8 + o3] = acc;
        }
    }
}

// ---------------------------------------------------------------------------
extern "C" void kernel_launch(void* const* d_in, const int* in_sizes, int n_in,
                              void* d_out, int out_size) {
    const float* x    = (const float*)d_in[0];
    const float* Wih  = (const float*)d_in[1];
    const float* Whh  = (const float*)d_in[2];
    const float* bih  = (const float*)d_in[3];
    const float* bhh  = (const float*)d_in[4];
    const float* Wafc = (const float*)d_in[5];
    const float* bafc = (const float*)d_in[6];
    const float* Wao  = (const float*)d_in[7];
    const float* bao  = (const float*)d_in[8];
    const float* Wc   = (const float*)d_in[9];
    const float* bc   = (const float*)d_in[10];
    const float* Wb   = (const float*)d_in[11];
    const float* bb   = (const float*)d_in[12];
    float* out = (float*)d_out;

    cudaFuncSetAttribute(kB,  cudaFuncAttributeMaxDynamicSharedMemorySize, SMEM_B);
    cudaFuncSetAttribute(kC1, cudaFuncAttributeMaxDynamicSharedMemorySize, SMEM_C1);
    cudaFuncSetAttribute(kC2, cudaFuncAttributeMaxDynamicSharedMemorySize, SMEM_C2);

    kA<<<dim3(4, 32, 128), 256>>>(x, Wih, bih, bhh);
    kB<<<128, 1024, SMEM_B>>>(Whh);
    kC1<<<4096, 256, SMEM_C1>>>(Wafc, bafc);
    kC2<<<4096, 256, SMEM_C2>>>(x, Wao, bao, Wc, bc, Wb, bb, out);
}

// round 13
// speedup vs baseline: 1.6294x; 1.6294x over previous
#include <cuda_runtime.h>
#include <math.h>
#include <stdint.h>

#define BB 128
#define TT 1024
#define DD 43
#define HH 256
#define G4 1024

// ---- static device scratch (allocation-free) ----
__device__ float g_xg[(size_t)TT * BB * G4];   // [t][b][g]
__device__ float g_hs[(size_t)BB * TT * HH];   // [b][t][k]
__device__ float g_a1[(size_t)BB * TT * HH];   // [tok][k]
__device__ int   g_flag[128 * 64];             // per (bg,slice) flag, 256B padded

__device__ __forceinline__ int ld_acquire(const int* p) {
    int v;
    asm volatile("ld.acquire.gpu.global.b32 %0, [%1];" : "=r"(v) : "l"(p));
    return v;
}
__device__ __forceinline__ void red_release_add(int* p, int v) {
    asm volatile("red.release.gpu.global.add.s32 [%0], %1;" :: "l"(p), "r"(v) : "memory");
}
__device__ __forceinline__ float sigf(float x) {
    float y;
    asm("tanh.approx.f32 %0, %1;" : "=f"(y) : "f"(0.5f * x));
    return 0.5f * y + 0.5f;
}
__device__ __forceinline__ float tanhf_fast(float x) {
    float y;
    asm("tanh.approx.f32 %0, %1;" : "=f"(y) : "f"(x));
    return y;
}

#define UNPACK2(lo, hi, s) asm("mov.b64 {%0, %1}, %2;" : "=f"(lo), "=f"(hi) : "l"(s))
#define FFMA2(acc, a, b)   asm("fma.rn.f32x2 %0, %1, %2, %0;" : "+l"(acc) : "l"(a), "l"(b))

// ---------------------------------------------------------------------------
__global__ void k_init() {
    if (threadIdx.x < 128) g_flag[threadIdx.x * 64] = 0;
}

// ---------------------------------------------------------------------------
// Kernel A: xg[t][b][g] = xin[b,t,:] . W_ih[g,:] + b_ih[g] + b_hh[g]
// ---------------------------------------------------------------------------
__global__ void __launch_bounds__(256) kA(const float* __restrict__ x,
                                          const float* __restrict__ Wih,
                                          const float* __restrict__ bih,
                                          const float* __restrict__ bhh) {
    __shared__ float xin[32 * 44];
    const int tid = threadIdx.x;
    const int g0  = blockIdx.x * 256;
    const int t0  = blockIdx.y * 32;
    const int b   = blockIdx.z;

    for (int e = tid; e < 32 * 44; e += 256) {
        int tt = e / 44, d = e % 44;
        int t = t0 + tt;
        float v = 0.0f;
        if (d < 35)      v = x[((size_t)b * TT + t) * DD + d];
        else if (d < 43) { if (t > 0) v = x[((size_t)b * TT + t - 1) * DD + d]; }
        xin[e] = v;
    }

    const int g = g0 + tid;
    float w[44];
#pragma unroll
    for (int d = 0; d < 43; d++) w[d] = Wih[g * DD + d];
    w[43] = 0.0f;
    const float bias = bih[g] + bhh[g];
    __syncthreads();

#pragma unroll 4
    for (int tt = 0; tt < 32; tt++) {
        const float* xr = &xin[tt * 44];
        float acc = bias;
#pragma unroll
        for (int d = 0; d < 44; d++) acc += w[d] * xr[d];
        g_xg[((size_t)(t0 + tt) * BB + b) * G4 + g] = acc;
    }
}

// ---------------------------------------------------------------------------
// Kernel B: persistent LSTM, 128 CTAs = 16 batch-groups x 8 hidden-slices.
// 512 threads = 8 K-eighth groups of 64. W in K-pair-major transposed smem,
// 2-row x 8-batch register tiles, f32x2 over K. Per-slice L2 flags; each
// K-group waits only on its own slice.
// ---------------------------------------------------------------------------
#define WP_OFF 0                       // WshP: [8 q][16 kpl][64 rp][2 i][2 j] = 32768 f
#define HP_OFF 32768                   // hshP: [128 kp][8 b][2 half] = 2048 f
#define GS_OFF (32768 + 2048)          // gsh:  [8 q][128 r][9] = 9216 f
#define SMEM_B ((GS_OFF + 9216) * 4)

__global__ void __launch_bounds__(512, 1) kB(const float* __restrict__ Whh) {
    extern __shared__ float sm[];
    float* hshP = sm + HP_OFF;
    float* gsh  = sm + GS_OFF;

    const int tid = threadIdx.x;
    const int cta = blockIdx.x;
    const int bg  = cta >> 3;          // batch group 0..15
    const int hsl = cta & 7;           // hidden slice 0..7
    const int b0  = bg * 8;

    const int q  = tid >> 6;           // K-eighth / slice group 0..7
    const int qt = tid & 63;
    const int rp = qt;                 // row-pair 0..63
    // pointwise mapping (tid < 256)
    const int ub = (tid >> 5) & 7;
    const int uk = tid & 31;
    // stage mapping within group
    const int stb = qt >> 3;           // batch 0..7
    const int stc = qt & 7;            // k-quad within slice

    // ---- W preload into pair-major transposed layout ----
    for (int idx = tid; idx < 32768; idx += 512) {
        int j   = idx & 1;
        int i   = (idx >> 1) & 1;
        int rpp = (idx >> 2) & 63;
        int kpl = (idx >> 8) & 15;
        int qq  = idx >> 12;
        int rl  = 2 * rpp + i;
        int R   = ((rl >> 5) << 8) + hsl * 32 + (rl & 31);
        int K   = qq * 32 + kpl * 2 + j;
        sm[WP_OFF + idx] = Whh[R * 256 + K];
    }
    for (int e = tid; e < 2048; e += 512) hshP[e] = 0.0f;   // h(-1) = 0

    int* flags = &g_flag[bg * 8 * 64];
    float c0 = 0.0f;

    // prefetch xg[0]
    float px0, px1, px2, px3;
    if (tid < 256) {
        const float* p = &g_xg[((size_t)b0 + ub) * G4 + hsl * 32 + uk];
        px0 = __ldcg(p);       px1 = __ldcg(p + 256);
        px2 = __ldcg(p + 512); px3 = __ldcg(p + 768);
    }
    __syncthreads();

    for (int t = 0; t < TT; t++) {
        // prefetch next step's xg (covered by stage+GEMM)
        float nx0, nx1, nx2, nx3;
        if (tid < 256) {
            int tn = (t + 1 < TT) ? (t + 1) : t;
            const float* p = &g_xg[((size_t)tn * BB + b0 + ub) * G4 + hsl * 32 + uk];
            nx0 = __ldcg(p);       nx1 = __ldcg(p + 256);
            nx2 = __ldcg(p + 512); nx3 = __ldcg(p + 768);
        }

        // ---- per-group: wait for own slice's flag, stage 1KB ----
        if (t > 0 && q != hsl) {
            if (qt == 0) {
                const int* fp = &flags[q * 64];
                while (ld_acquire(fp) < t) { }
            }
            asm volatile("bar.sync %0, 64;" :: "r"(1 + q) : "memory");
            {
                float4 v = __ldcg((const float4*)
                    &g_hs[(((size_t)(b0 + stb)) * TT + (t - 1)) * HH + q * 32 + stc * 4]);
                int kp = (q * 32 + stc * 4) >> 1;     // even base
                hshP[(kp * 8 + stb) * 2 + 0]       = v.x;
                hshP[(kp * 8 + stb) * 2 + 1]       = v.y;
                hshP[((kp + 1) * 8 + stb) * 2 + 0] = v.z;
                hshP[((kp + 1) * 8 + stb) * 2 + 1] = v.w;
            }
            asm volatile("bar.sync %0, 64;" :: "r"(1 + q) : "memory");
        }

        // ---- GEMM: 2 rows x 8 batches x 32 K, f32x2 pairs over K ----
        {
            unsigned long long acc[16];
#pragma unroll
            for (int z = 0; z < 16; z++) acc[z] = 0ull;
            const ulonglong2* wp = (const ulonglong2*)(sm + WP_OFF) + q * 1024 + rp;
            const ulonglong2* hp = (const ulonglong2*)hshP + q * 64;
#pragma unroll
            for (int kpl = 0; kpl < 16; kpl++) {
                ulonglong2 w  = wp[kpl * 64];
                ulonglong2 hA = hp[kpl * 4 + 0];
                ulonglong2 hB = hp[kpl * 4 + 1];
                ulonglong2 hC = hp[kpl * 4 + 2];
                ulonglong2 hD = hp[kpl * 4 + 3];
                FFMA2(acc[0],  w.x, hA.x); FFMA2(acc[1],  w.x, hA.y);
                FFMA2(acc[2],  w.x, hB.x); FFMA2(acc[3],  w.x, hB.y);
                FFMA2(acc[4],  w.x, hC.x); FFMA2(acc[5],  w.x, hC.y);
                FFMA2(acc[6],  w.x, hD.x); FFMA2(acc[7],  w.x, hD.y);
                FFMA2(acc[8],  w.y, hA.x); FFMA2(acc[9],  w.y, hA.y);
                FFMA2(acc[10], w.y, hB.x); FFMA2(acc[11], w.y, hB.y);
                FFMA2(acc[12], w.y, hC.x); FFMA2(acc[13], w.y, hC.y);
                FFMA2(acc[14], w.y, hD.x); FFMA2(acc[15], w.y, hD.y);
            }
#pragma unroll
            for (int i = 0; i < 2; i++) {
                float* gp = &gsh[q * 1152 + (2 * rp + i) * 9];
#pragma unroll
                for (int b = 0; b < 8; b++) {
                    float lo, hi;
                    UNPACK2(lo, hi, acc[i * 8 + b]);
                    gp[b] = lo + hi;
                }
            }
        }
        __syncthreads();

        // ---- pointwise LSTM update (tid < 256) ----
        if (tid < 256) {
            float gi = px0, gf = px1, gg = px2, go = px3;
#pragma unroll
            for (int qq = 0; qq < 8; qq++) {
                const float* g = &gsh[qq * 1152 + uk * 9 + ub];
                gi += g[0];
                gf += g[32 * 9];
                gg += g[64 * 9];
                go += g[96 * 9];
            }
            gi = sigf(gi); gf = sigf(gf);
            gg = tanhf_fast(gg); go = sigf(go);
            c0 = gf * c0 + gi * gg;
            float h = go * tanhf_fast(c0);
            g_hs[(((size_t)(b0 + ub)) * TT + t) * HH + hsl * 32 + uk] = h;
            int K = hsl * 32 + uk;
            hshP[((K >> 1) * 8 + ub) * 2 + (K & 1)] = h;   // own slice locally
            px0 = nx0; px1 = nx1; px2 = nx2; px3 = nx3;
            asm volatile("bar.sync 9, 256;" ::: "memory");  // all h writes done
            if (tid == 0 && t + 1 < TT)
                red_release_add(&flags[hsl * 64], 1);
        }
        __syncthreads();
    }
}

// ---------------------------------------------------------------------------
// Kernel C1: a1 = relu(hs @ W_afc1^T + b).  Block: 32 tokens x 256 outputs.
// ---------------------------------------------------------------------------
#define SMEM_C1 ((32 * 256 + 256 * 68) * 4)

__global__ void __launch_bounds__(256) kC1(const float* __restrict__ Wa,
                                           const float* __restrict__ ba) {
    extern __shared__ float sm[];
    float* hsh = sm;               // [32][256]
    float* Ws  = sm + 32 * 256;    // [256][68] current K-chunk

    const int tid  = threadIdx.x;
    const int tok0 = blockIdx.x * 32;

    for (int e = tid; e < 32 * 256; e += 256)
        hsh[e] = g_hs[(size_t)tok0 * 256 + e];

    float acc[32];
    const float bias = ba[tid];
#pragma unroll
    for (int i = 0; i < 32; i++) acc[i] = bias;

    for (int kc = 0; kc < 4; kc++) {
        __syncthreads();
        for (int e = tid; e < 256 * 64; e += 256) {
            int j = e >> 6, kk = e & 63;
            Ws[j * 68 + kk] = Wa[j * 256 + kc * 64 + kk];
        }
        __syncthreads();
        const float4* wp = (const float4*)&Ws[tid * 68];
#pragma unroll
        for (int q = 0; q < 16; q++) {
            float4 w4 = wp[q];
            const int kbase = kc * 64 + q * 4;
#pragma unroll 8
            for (int tt = 0; tt < 32; tt++) {
                float4 h = *(const float4*)&hsh[tt * 256 + kbase];
                acc[tt] += w4.x * h.x + w4.y * h.y + w4.z * h.z + w4.w * h.w;
            }
        }
    }
#pragma unroll
    for (int tt = 0; tt < 32; tt++)
        g_a1[((size_t)(tok0 + tt)) * 256 + tid] = fmaxf(acc[tt], 0.0f);
}

// ---------------------------------------------------------------------------
// Kernel C2: cont / bin / act heads.
// ---------------------------------------------------------------------------
#define CONT_BASE 0
#define BIN_BASE  (128 * 1024 * 50)
#define ACT_BASE  (BIN_BASE + 128 * 1024 * 10)
#define SMEM_C2 ((32 * 268 + 32 * 256 + 50 * 268 + 10 * 268 + 8 * 256 + 68) * 4)

__global__ void __launch_bounds__(256) kC2(const float* __restrict__ x,
                                           const float* __restrict__ Wao,
                                           const float* __restrict__ bao,
                                           const float* __restrict__ Wc,
                                           const float* __restrict__ bc,
                                           const float* __restrict__ Wb,
                                           const float* __restrict__ bb,
                                           float* __restrict__ out) {
    extern __shared__ float sm[];
    float* pred = sm;                   // [32][268]  (h | cur)
    float* a1s  = pred + 32 * 268;      // [32][256]
    float* Wcs  = a1s  + 32 * 256;      // [50][268]
    float* Wbs  = Wcs  + 50 * 268;      // [10][268]
    float* Was  = Wbs  + 10 * 268;      // [8][256]
    float* bcs  = Was  + 8 * 256;       // 50
    float* bbs  = bcs + 50;             // 10
    float* bas  = bbs + 10;             // 8

    const int tid  = threadIdx.x;
    const int tok0 = blockIdx.x * 32;

    for (int e = tid; e < 32 * 256; e += 256) {
        int tt = e >> 8, k = e & 255;
        pred[tt * 268 + k] = g_hs[(size_t)tok0 * 256 + e];
        a1s[e]             = g_a1[(size_t)tok0 * 256 + e];
    }
    if (tid < 32 * 8) {
        int tt = tid >> 3, j = tid & 7;
        pred[tt * 268 + 256 + j] = x[((size_t)(tok0 + tt)) * DD + 35 + j];
    }
    for (int e = tid; e < 50 * 264; e += 256) {
        int o = e / 264, d = e % 264;
        Wcs[o * 268 + d] = Wc[e];
    }
    for (int e = tid; e < 10 * 264; e += 256) {
        int o = e / 264, d = e % 264;
        Wbs[o * 268 + d] = Wb[e];
    }
    for (int e = tid; e < 8 * 256; e += 256) Was[e] = Wao[e];
    if (tid < 50) bcs[tid] = bc[tid];
    if (tid < 10) bbs[tid] = bb[tid];
    if (tid < 8)  bas[tid] = bao[tid];
    __syncthreads();

    for (int idx = tid; idx < 32 * 68; idx += 256) {
        const int tt   = idx / 68;
        const int o    = idx % 68;
        const int gtok = tok0 + tt;
        if (o < 50) {
            float acc = bcs[o];
            const float4* wp = (const float4*)&Wcs[o * 268];
            const float4* pp = (const float4*)&pred[tt * 268];
#pragma unroll 11
            for (int q = 0; q < 66; q++) {
                float4 w = wp[q], p = pp[q];
                acc += w.x * p.x + w.y * p.y + w.z * p.z + w.w * p.w;
            }
            out[CONT_BASE + (size_t)gtok * 50 + o] = acc;
        } else if (o < 60) {
            const int o2 = o - 50;
            float acc = bbs[o2];
            const float4* wp = (const float4*)&Wbs[o2 * 268];
            const float4* pp = (const float4*)&pred[tt * 268];
#pragma unroll 11
            for (int q = 0; q < 66; q++) {
                float4 w = wp[q], p = pp[q];
                acc += w.x * p.x + w.y * p.y + w.z * p.z + w.w * p.w;
            }
            out[BIN_BASE + (size_t)gtok * 10 + o2] = 1.0f / (1.0f + __expf(-acc));
        } else {
            const int o3 = o - 60;
            float acc = bas[o3];
            const float4* wp = (const float4*)&Was[o3 * 256];
            const float4* pp = (const float4*)&a1s[tt * 256];
#pragma unroll 16
            for (int q = 0; q < 64; q++) {
                float4 w = wp[q], p = pp[q];
                acc += w.x * p.x + w.y * p.y + w.z * p.z + w.w * p.w;
            }
            out[ACT_BASE + (size_t)gtok * 8 + o3] = acc;
        }
    }
}

// ---------------------------------------------------------------------------
extern "C" void kernel_launch(void* const* d_in, const int* in_sizes, int n_in,
                              void* d_out, int out_size) {
    const float* x    = (const float*)d_in[0];
    const float* Wih  = (const float*)d_in[1];
    const float* Whh  = (const float*)d_in[2];
    const float* bih  = (const float*)d_in[3];
    const float* bhh  = (const float*)d_in[4];
    const float* Wafc = (const float*)d_in[5];
    const float* bafc = (const float*)d_in[6];
    const float* Wao  = (const float*)d_in[7];
    const float* bao  = (const float*)d_in[8];
    const float* Wc   = (const float*)d_in[9];
    const float* bc   = (const float*)d_in[10];
    const float* Wb   = (const float*)d_in[11];
    const float* bb   = (const float*)d_in[12];
    float* out = (float*)d_out;

    cudaFuncSetAttribute(kB,  cudaFuncAttributeMaxDynamicSharedMemorySize, SMEM_B);
    cudaFuncSetAttribute(kC1, cudaFuncAttributeMaxDynamicSharedMemorySize, SMEM_C1);
    cudaFuncSetAttribute(kC2, cudaFuncAttributeMaxDynamicSharedMemorySize, SMEM_C2);

    k_init<<<1, 128>>>();
    kA<<<dim3(4, 32, 128), 256>>>(x, Wih, bih, bhh);
    kB<<<128, 512, SMEM_B>>>(Whh);
    kC1<<<4096, 256, SMEM_C1>>>(Wafc, bafc);
    kC2<<<4096, 256, SMEM_C2>>>(x, Wao, bao, Wc, bc, Wb, bb, out);
}

// round 15
// speedup vs baseline: 1.7814x; 1.0933x over previous
#include <cuda_runtime.h>
#include <cuda_bf16.h>
#include <math.h>
#include <stdint.h>

#define BB 128
#define TT 1024
#define DD 43
#define HH 256
#define G4 1024

// ---- static device scratch (allocation-free) ----
__device__ float g_xg[(size_t)TT * BB * G4];   // [t][b][g]
__device__ float g_hs[(size_t)BB * TT * HH];   // [b][t][k]
__device__ float g_a1[(size_t)BB * TT * HH];   // [tok][k]
__device__ int   g_flag[128 * 64];             // per (bg,slice) flag, 256B padded

__device__ __forceinline__ int ld_acquire(const int* p) {
    int v;
    asm volatile("ld.acquire.gpu.global.b32 %0, [%1];" : "=r"(v) : "l"(p));
    return v;
}
__device__ __forceinline__ void red_release_add(int* p, int v) {
    asm volatile("red.release.gpu.global.add.s32 [%0], %1;" :: "l"(p), "r"(v) : "memory");
}
__device__ __forceinline__ float sigf(float x) {
    float y;
    asm("tanh.approx.f32 %0, %1;" : "=f"(y) : "f"(0.5f * x));
    return 0.5f * y + 0.5f;
}
__device__ __forceinline__ float tanhf_fast(float x) {
    float y;
    asm("tanh.approx.f32 %0, %1;" : "=f"(y) : "f"(x));
    return y;
}
__device__ __forceinline__ uint32_t smem_u32(const void* p) {
    uint32_t a;
    asm("{ .reg .u64 t; cvta.to.shared.u64 t, %1; cvt.u32.u64 %0, t; }" : "=r"(a) : "l"(p));
    return a;
}

#define LDSM4(r0, r1, r2, r3, addr) \
    asm volatile("ldmatrix.sync.aligned.m8n8.x4.shared.b16 {%0,%1,%2,%3}, [%4];" \
                 : "=r"(r0), "=r"(r1), "=r"(r2), "=r"(r3) : "r"(addr))
#define LDSM2T(r0, r1, addr) \
    asm volatile("ldmatrix.sync.aligned.m8n8.x2.trans.shared.b16 {%0,%1}, [%2];" \
                 : "=r"(r0), "=r"(r1) : "r"(addr))
#define MMA_BF16(c0, c1, c2, c3, a0, a1, a2, a3, b0, b1) \
    asm volatile("mma.sync.aligned.m16n8k16.row.col.f32.bf16.bf16.f32 " \
                 "{%0,%1,%2,%3}, {%4,%5,%6,%7}, {%8,%9}, {%0,%1,%2,%3};" \
                 : "+f"(c0), "+f"(c1), "+f"(c2), "+f"(c3) \
                 : "r"(a0), "r"(a1), "r"(a2), "r"(a3), "r"(b0), "r"(b1))

// ---------------------------------------------------------------------------
__global__ void k_init() {
    if (threadIdx.x < 128) g_flag[threadIdx.x * 64] = 0;
}

// ---------------------------------------------------------------------------
// Kernel A: xg[t][b][g] = xin[b,t,:] . W_ih[g,:] + b_ih[g] + b_hh[g]
// ---------------------------------------------------------------------------
__global__ void __launch_bounds__(256) kA(const float* __restrict__ x,
                                          const float* __restrict__ Wih,
                                          const float* __restrict__ bih,
                                          const float* __restrict__ bhh) {
    __shared__ float xin[32 * 44];
    const int tid = threadIdx.x;
    const int g0  = blockIdx.x * 256;
    const int t0  = blockIdx.y * 32;
    const int b   = blockIdx.z;

    for (int e = tid; e < 32 * 44; e += 256) {
        int tt = e / 44, d = e % 44;
        int t = t0 + tt;
        float v = 0.0f;
        if (d < 35)      v = x[((size_t)b * TT + t) * DD + d];
        else if (d < 43) { if (t > 0) v = x[((size_t)b * TT + t - 1) * DD + d]; }
        xin[e] = v;
    }

    const int g = g0 + tid;
    float w[44];
#pragma unroll
    for (int d = 0; d < 43; d++) w[d] = Wih[g * DD + d];
    w[43] = 0.0f;
    const float bias = bih[g] + bhh[g];
    __syncthreads();

#pragma unroll 4
    for (int tt = 0; tt < 32; tt++) {
        const float* xr = &xin[tt * 44];
        float acc = bias;
#pragma unroll
        for (int d = 0; d < 44; d++) acc += w[d] * xr[d];
        g_xg[((size_t)(t0 + tt) * BB + b) * G4 + g] = acc;
    }
}

// ---------------------------------------------------------------------------
// Kernel B: persistent LSTM, 128 CTAs = 16 batch-groups x 8 hidden-slices.
// Gate GEMM on HMMA (mma.sync m16n8k16 bf16, hi/lo 3-product split, fp32 acc).
// W planes [128r][256K] bf16 stride 528B; h planes [256K][8b] bf16 (16B rows).
// R13 sync fabric: per-slice L2 flags, 8 stage groups of 64, bar9 + release.
// Local row r: gate = r&3, klocal = r>>2 -> global W row = gate*256+hsl*32+klocal.
// ---------------------------------------------------------------------------
#define WS      528                    // W row stride, bytes
#define WHI_OFF 0                      // 67584 B
#define WLO_OFF 67584                  // 67584 B
#define BHI_OFF 135168                 // 4096 B
#define BLO_OFF 139264                 // 4096 B
#define GSH_OFF 143360                 // 2*1280 floats = 10240 B
#define SMEM_B  153600

__global__ void __launch_bounds__(512, 1) kB(const float* __restrict__ Whh) {
    extern __shared__ char smc[];
    float* gsh = (float*)(smc + GSH_OFF);   // [2 half][128 r][10]

    const int tid  = threadIdx.x;
    const int wid  = tid >> 5;
    const int lane = tid & 31;
    const int cta = blockIdx.x;
    const int bg  = cta >> 3;          // batch group 0..15
    const int hsl = cta & 7;           // hidden slice 0..7
    const int b0  = bg * 8;

    const uint32_t smb = smem_u32(smc);

    // ---- W hi/lo preload: row r, col k at byte r*WS + k*2 ----
    for (int idx = tid; idx < 128 * 256; idx += 512) {
        int r = idx >> 8, k = idx & 255;
        int R = (r & 3) * 256 + hsl * 32 + (r >> 2);
        float w = Whh[R * 256 + k];
        __nv_bfloat16 hi = __float2bfloat16(w);
        __nv_bfloat16 lo = __float2bfloat16(w - __bfloat162float(hi));
        *(__nv_bfloat16*)(smc + WHI_OFF + r * WS + k * 2) = hi;
        *(__nv_bfloat16*)(smc + WLO_OFF + r * WS + k * 2) = lo;
    }
    // zero h planes (h(-1) = 0): 2 x 4096 B
    for (int e = tid; e < 2048; e += 512)
        ((uint32_t*)(smc + BHI_OFF))[e] = 0u;   // covers BHI+BLO (contiguous)
    __syncthreads();

    // role mappings
    const int q  = tid >> 6;           // stage group / slice 0..7
    const int qt = tid & 63;
    const int sb = qt >> 3;            // batch 0..7 (stage)
    const int sj = qt & 7;             // k-quad within slice (stage)
    const int ub = (tid >> 5) & 7;     // batch (pointwise, tid<256)
    const int uk = tid & 31;           // local k (pointwise)

    // MMA mapping: row tile rt = wid>>1 (16 rows), K-half khm = wid&1 (128 K)
    const int rt  = wid >> 1;
    const int khm = wid & 1;
    const int arow  = rt * 16 + ((lane >> 3) & 1) * 8 + (lane & 7);
    const int acol8 = (lane >> 4) * 8;
    const uint32_t aHi = smb + WHI_OFF + arow * WS + (khm * 128 + acol8) * 2;
    const uint32_t aLo = smb + WLO_OFF + arow * WS + (khm * 128 + acol8) * 2;
    const uint32_t bHi = smb + BHI_OFF + (khm * 128 + (lane & 15)) * 16;
    const uint32_t bLo = smb + BLO_OFF + (khm * 128 + (lane & 15)) * 16;
    const int dg = lane >> 2, dt = lane & 3;    // D frag coords

    int* flags = &g_flag[bg * 8 * 64];
    float c0s = 0.0f;

    // prefetch xg[0]
    float px0, px1, px2, px3;
    if (tid < 256) {
        const float* p = &g_xg[((size_t)b0 + ub) * G4 + hsl * 32 + uk];
        px0 = __ldcg(p);       px1 = __ldcg(p + 256);
        px2 = __ldcg(p + 512); px3 = __ldcg(p + 768);
    }

    for (int t = 0; t < TT; t++) {
        // prefetch next step's xg
        float nx0, nx1, nx2, nx3;
        if (tid < 256) {
            int tn = (t + 1 < TT) ? (t + 1) : t;
            const float* p = &g_xg[((size_t)tn * BB + b0 + ub) * G4 + hsl * 32 + uk];
            nx0 = __ldcg(p);       nx1 = __ldcg(p + 256);
            nx2 = __ldcg(p + 512); nx3 = __ldcg(p + 768);
        }

        // ---- stage remote slices of h(t-1) -> B planes ([k][b] bf16) ----
        if (t > 0 && q != hsl) {
            if (qt == 0) {
                const int* fp = &flags[q * 64];
                while (ld_acquire(fp) < t) { }
            }
            asm volatile("bar.sync %0, 64;" :: "r"(1 + q) : "memory");
            {
                int k0 = q * 32 + sj * 4;
                float4 v = __ldcg((const float4*)
                    &g_hs[(((size_t)(b0 + sb)) * TT + (t - 1)) * HH + k0]);
                float hv[4] = {v.x, v.y, v.z, v.w};
#pragma unroll
                for (int u = 0; u < 4; u++) {
                    int off = ((k0 + u) * 8 + sb) * 2;
                    __nv_bfloat16 hi = __float2bfloat16(hv[u]);
                    __nv_bfloat16 lo = __float2bfloat16(hv[u] - __bfloat162float(hi));
                    *(__nv_bfloat16*)(smc + BHI_OFF + off) = hi;
                    *(__nv_bfloat16*)(smc + BLO_OFF + off) = lo;
                }
            }
        }
        __syncthreads();   // B complete (stage + own-slice writes from t-1)

        // ---- HMMA: 8 K-chunks x 3 products, fp32 accumulate ----
        {
            float c0 = 0.f, c1 = 0.f, c2 = 0.f, c3 = 0.f;
#pragma unroll
            for (int kc = 0; kc < 8; kc++) {
                uint32_t ah0, ah1, ah2, ah3, al0, al1, al2, al3;
                uint32_t bh0, bh1, bl0, bl1;
                LDSM4(ah0, ah1, ah2, ah3, aHi + kc * 32);
                LDSM4(al0, al1, al2, al3, aLo + kc * 32);
                LDSM2T(bh0, bh1, bHi + kc * 256);
                LDSM2T(bl0, bl1, bLo + kc * 256);
                MMA_BF16(c0, c1, c2, c3, ah0, ah1, ah2, ah3, bh0, bh1);
                MMA_BF16(c0, c1, c2, c3, ah0, ah1, ah2, ah3, bl0, bl1);
                MMA_BF16(c0, c1, c2, c3, al0, al1, al2, al3, bh0, bh1);
            }
            // D frag -> gsh: rows rt*16+dg (+8), cols (batches) dt*2 (+1)
            float* gp = &gsh[khm * 1280 + (rt * 16 + dg) * 10 + dt * 2];
            *(float2*)gp        = make_float2(c0, c1);
            *(float2*)(gp + 80) = make_float2(c2, c3);   // row +8
        }
        __syncthreads();   // gates in gsh

        // ---- pointwise LSTM update (tid < 256) ----
        if (tid < 256) {
            const int o = (uk * 4) * 10 + ub;
            float gi = sigf(      px0 + gsh[o]      + gsh[1280 + o]);
            float gf = sigf(      px1 + gsh[o + 10] + gsh[1290 + o]);
            float gg = tanhf_fast(px2 + gsh[o + 20] + gsh[1300 + o]);
            float go = sigf(      px3 + gsh[o + 30] + gsh[1310 + o]);
            c0s = gf * c0s + gi * gg;
            float h = go * tanhf_fast(c0s);
            g_hs[(((size_t)(b0 + ub)) * TT + t) * HH + hsl * 32 + uk] = h;
            // own slice -> B planes for next step
            int off = ((hsl * 32 + uk) * 8 + ub) * 2;
            __nv_bfloat16 hi = __float2bfloat16(h);
            __nv_bfloat16 lo = __float2bfloat16(h - __bfloat162float(hi));
            *(__nv_bfloat16*)(smc + BHI_OFF + off) = hi;
            *(__nv_bfloat16*)(smc + BLO_OFF + off) = lo;
            px0 = nx0; px1 = nx1; px2 = nx2; px3 = nx3;
            asm volatile("bar.sync 9, 256;" ::: "memory");   // h STGs done
            if (tid == 0 && t + 1 < TT)
                red_release_add(&flags[hsl * 64], 1);
        }
    }
}

// ---------------------------------------------------------------------------
// Kernel C1: a1 = relu(hs @ W_afc1^T + b).  Block: 32 tokens x 256 outputs.
// ---------------------------------------------------------------------------
#define SMEM_C1 ((32 * 256 + 256 * 68) * 4)

__global__ void __launch_bounds__(256) kC1(const float* __restrict__ Wa,
                                           const float* __restrict__ ba) {
    extern __shared__ float sm[];
    float* hsh = sm;               // [32][256]
    float* Ws  = sm + 32 * 256;    // [256][68] current K-chunk

    const int tid  = threadIdx.x;
    const int tok0 = blockIdx.x * 32;

    for (int e = tid; e < 32 * 256; e += 256)
        hsh[e] = g_hs[(size_t)tok0 * 256 + e];

    float acc[32];
    const float bias = ba[tid];
#pragma unroll
    for (int i = 0; i < 32; i++) acc[i] = bias;

    for (int kc = 0; kc < 4; kc++) {
        __syncthreads();
        for (int e = tid; e < 256 * 64; e += 256) {
            int j = e >> 6, kk = e & 63;
            Ws[j * 68 + kk] = Wa[j * 256 + kc * 64 + kk];
        }
        __syncthreads();
        const float4* wp = (const float4*)&Ws[tid * 68];
#pragma unroll
        for (int q = 0; q < 16; q++) {
            float4 w4 = wp[q];
            const int kbase = kc * 64 + q * 4;
#pragma unroll 8
            for (int tt = 0; tt < 32; tt++) {
                float4 h = *(const float4*)&hsh[tt * 256 + kbase];
                acc[tt] += w4.x * h.x + w4.y * h.y + w4.z * h.z + w4.w * h.w;
            }
        }
    }
#pragma unroll
    for (int tt = 0; tt < 32; tt++)
        g_a1[((size_t)(tok0 + tt)) * 256 + tid] = fmaxf(acc[tt], 0.0f);
}

// ---------------------------------------------------------------------------
// Kernel C2: cont / bin / act heads.
// ---------------------------------------------------------------------------
#define CONT_BASE 0
#define BIN_BASE  (128 * 1024 * 50)
#define ACT_BASE  (BIN_BASE + 128 * 1024 * 10)
#define SMEM_C2 ((32 * 268 + 32 * 256 + 50 * 268 + 10 * 268 + 8 * 256 + 68) * 4)

__global__ void __launch_bounds__(256) kC2(const float* __restrict__ x,
                                           const float* __restrict__ Wao,
                                           const float* __restrict__ bao,
                                           const float* __restrict__ Wc,
                                           const float* __restrict__ bc,
                                           const float* __restrict__ Wb,
                                           const float* __restrict__ bb,
                                           float* __restrict__ out) {
    extern __shared__ float sm[];
    float* pred = sm;                   // [32][268]  (h | cur)
    float* a1s  = pred + 32 * 268;      // [32][256]
    float* Wcs  = a1s  + 32 * 256;      // [50][268]
    float* Wbs  = Wcs  + 50 * 268;      // [10][268]
    float* Was  = Wbs  + 10 * 268;      // [8][256]
    float* bcs  = Was  + 8 * 256;       // 50
    float* bbs  = bcs + 50;             // 10
    float* bas  = bbs + 10;             // 8

    const int tid  = threadIdx.x;
    const int tok0 = blockIdx.x * 32;

    for (int e = tid; e < 32 * 256; e += 256) {
        int tt = e >> 8, k = e & 255;
        pred[tt * 268 + k] = g_hs[(size_t)tok0 * 256 + e];
        a1s[e]             = g_a1[(size_t)tok0 * 256 + e];
    }
    if (tid < 32 * 8) {
        int tt = tid >> 3, j = tid & 7;
        pred[tt * 268 + 256 + j] = x[((size_t)(tok0 + tt)) * DD + 35 + j];
    }
    for (int e = tid; e < 50 * 264; e += 256) {
        int o = e / 264, d = e % 264;
        Wcs[o * 268 + d] = Wc[e];
    }
    for (int e = tid; e < 10 * 264; e += 256) {
        int o = e / 264, d = e % 264;
        Wbs[o * 268 + d] = Wb[e];
    }
    for (int e = tid; e < 8 * 256; e += 256) Was[e] = Wao[e];
    if (tid < 50) bcs[tid] = bc[tid];
    if (tid < 10) bbs[tid] = bb[tid];
    if (tid < 8)  bas[tid] = bao[tid];
    __syncthreads();

    for (int idx = tid; idx < 32 * 68; idx += 256) {
        const int tt   = idx / 68;
        const int o    = idx % 68;
        const int gtok = tok0 + tt;
        if (o < 50) {
            float acc = bcs[o];
            const float4* wp = (const float4*)&Wcs[o * 268];
            const float4* pp = (const float4*)&pred[tt * 268];
#pragma unroll 11
            for (int q = 0; q < 66; q++) {
                float4 w = wp[q], p = pp[q];
                acc += w.x * p.x + w.y * p.y + w.z * p.z + w.w * p.w;
            }
            out[CONT_BASE + (size_t)gtok * 50 + o] = acc;
        } else if (o < 60) {
            const int o2 = o - 50;
            float acc = bbs[o2];
            const float4* wp = (const float4*)&Wbs[o2 * 268];
            const float4* pp = (const float4*)&pred[tt * 268];
#pragma unroll 11
            for (int q = 0; q < 66; q++) {
                float4 w = wp[q], p = pp[q];
                acc += w.x * p.x + w.y * p.y + w.z * p.z + w.w * p.w;
            }
            out[BIN_BASE + (size_t)gtok * 10 + o2] = 1.0f / (1.0f + __expf(-acc));
        } else {
            const int o3 = o - 60;
            float acc = bas[o3];
            const float4* wp = (const float4*)&Was[o3 * 256];
            const float4* pp = (const float4*)&a1s[tt * 256];
#pragma unroll 16
            for (int q = 0; q < 64; q++) {
                float4 w = wp[q], p = pp[q];
                acc += w.x * p.x + w.y * p.y + w.z * p.z + w.w * p.w;
            }
            out[ACT_BASE + (size_t)gtok * 8 + o3] = acc;
        }
    }
}

// ---------------------------------------------------------------------------
extern "C" void kernel_launch(void* const* d_in, const int* in_sizes, int n_in,
                              void* d_out, int out_size) {
    const float* x    = (const float*)d_in[0];
    const float* Wih  = (const float*)d_in[1];
    const float* Whh  = (const float*)d_in[2];
    const float* bih  = (const float*)d_in[3];
    const float* bhh  = (const float*)d_in[4];
    const float* Wafc = (const float*)d_in[5];
    const float* bafc = (const float*)d_in[6];
    const float* Wao  = (const float*)d_in[7];
    const float* bao  = (const float*)d_in[8];
    const float* Wc   = (const float*)d_in[9];
    const float* bc   = (const float*)d_in[10];
    const float* Wb   = (const float*)d_in[11];
    const float* bb   = (const float*)d_in[12];
    float* out = (float*)d_out;

    cudaFuncSetAttribute(kB,  cudaFuncAttributeMaxDynamicSharedMemorySize, SMEM_B);
    cudaFuncSetAttribute(kC1, cudaFuncAttributeMaxDynamicSharedMemorySize, SMEM_C1);
    cudaFuncSetAttribute(kC2, cudaFuncAttributeMaxDynamicSharedMemorySize, SMEM_C2);

    k_init<<<1, 128>>>();
    kA<<<dim3(4, 32, 128), 256>>>(x, Wih, bih, bhh);
    kB<<<128, 512, SMEM_B>>>(Whh);
    kC1<<<4096, 256, SMEM_C1>>>(Wafc, bafc);
    kC2<<<4096, 256, SMEM_C2>>>(x, Wao, bao, Wc, bc, Wb, bb, out);
}